// round 16
// baseline (speedup 1.0000x reference)
#include <cuda_runtime.h>
#include <cuda_fp16.h>
#include <cstdint>
#include <stdint.h>
#include <math.h>

#define L_SEQ 4096
#define D_MODEL 1536
#define N_HEADS 12
#define D_HEAD 128
#define C_HALF 64   // d/2
#define ROPE_C1 22
#define ROPE_C2 21
#define W_ELEMS (D_MODEL * D_MODEL)
#define ML_OFF ((size_t)L_SEQ * N_HEADS * 2)

// ---------------- scratch (no allocations allowed) ----------------
__device__ float g_q[L_SEQ * D_MODEL];   // f32 q from GEMM; later: partial O (z=0)
__device__ float g_k[L_SEQ * D_MODEL];   // f32 k from GEMM; later: partial O (z=1)
__device__ __half g_qh[L_SEQ * D_MODEL]; // fp16 q (normed+rope+scaled)
__device__ __half g_kh[L_SEQ * D_MODEL]; // fp16 k
__device__ __half g_vh[L_SEQ * D_MODEL]; // fp16 v
__device__ __half g_wh[4 * W_ELEMS];     // fp16 Wq,Wk,Wv,Wo
__device__ float g_ml[2 * L_SEQ * N_HEADS * 2];  // (m,l) per z,row,head (log2)

// ---------------- helpers ----------------
__device__ __forceinline__ float ex2(float x) {
  float y;
  asm("ex2.approx.f32 %0, %1;" : "=f"(y) : "f"(x));
  return y;
}

__device__ __forceinline__ void mma16(float* c, const unsigned* a,
                                      const unsigned* b) {
  asm volatile(
      "mma.sync.aligned.m16n8k16.row.col.f32.f16.f16.f32 "
      "{%0,%1,%2,%3},{%4,%5,%6,%7},{%8,%9},{%0,%1,%2,%3};\n"
      : "+f"(c[0]), "+f"(c[1]), "+f"(c[2]), "+f"(c[3])
      : "r"(a[0]), "r"(a[1]), "r"(a[2]), "r"(a[3]), "r"(b[0]), "r"(b[1]));
}

#define LDSM4(r0, r1, r2, r3, addr)                                      \
  asm volatile("ldmatrix.sync.aligned.m8n8.x4.shared.b16 {%0,%1,%2,%3},[%4];" \
               : "=r"(r0), "=r"(r1), "=r"(r2), "=r"(r3) : "r"(addr))
#define LDSM4T(r0, r1, r2, r3, addr)                                     \
  asm volatile(                                                          \
      "ldmatrix.sync.aligned.m8n8.x4.trans.shared.b16 {%0,%1,%2,%3},[%4];" \
      : "=r"(r0), "=r"(r1), "=r"(r2), "=r"(r3) : "r"(addr))

// cp.async helpers (16B, cache-global)
#define CP_ASYNC16(dst, src)                                        \
  asm volatile("cp.async.cg.shared.global [%0], [%1], 16;" ::       \
                   "r"(dst), "l"(src))
#define CP_COMMIT() asm volatile("cp.async.commit_group;" ::: "memory")
#define CP_WAIT0() asm volatile("cp.async.wait_group 0;" ::: "memory")
#define CP_WAIT1() asm volatile("cp.async.wait_group 1;" ::: "memory")

// ---------------- fp16 conversion of weights ----------------
__global__ __launch_bounds__(256) void to_half(
    const float* __restrict__ wq, const float* __restrict__ wk,
    const float* __restrict__ wv, const float* __restrict__ wo) {
  const int zi = blockIdx.z;
  const float4* src = (const float4*)((zi == 0)   ? wq
                                      : (zi == 1) ? wk
                                      : (zi == 2) ? wv
                                                  : wo);
  __half2* dst = ((__half2*)g_wh) + (size_t)zi * (W_ELEMS / 2);
  int idx = blockIdx.x * 256 + threadIdx.x;
  if (idx < W_ELEMS / 4) {
    float4 t = src[idx];
    dst[2 * idx] = __floats2half2_rn(t.x, t.y);
    dst[2 * idx + 1] = __floats2half2_rn(t.z, t.w);
  }
}

// ---------------- fp16 GEMM: C[M,N] = A * W^T + bias ----------------
// 128x128 tile, BK=64, 256 threads (8 warps, 2m x 4n), warp 64x32.
// AMODE: 0 = A fp16; 1 = A f32 (convert on load); 2 = A merged split-KV
// partials (Oa, Ob f32 + ml in log2 space -> merged fp16 on load).
// zi selects weights/bias/output; zi==2 writes fp16 (v), else f32.
#define GSW 36  // row stride in words (64 halves + 8 pad = 144B)
template <int AMODE>
__global__ __launch_bounds__(256, 2) void gemm_f16(
    const __half* __restrict__ Ah, const float* __restrict__ Af,
    const float* __restrict__ Oa, const float* __restrict__ Ob,
    const float* __restrict__ mlp,
    const __half* __restrict__ Wm0, const __half* __restrict__ Wm1,
    const __half* __restrict__ Wm2,
    const float* __restrict__ bz0, const float* __restrict__ bz1,
    const float* __restrict__ bz2,
    float* __restrict__ Cf0, float* __restrict__ Cf1,
    __half* __restrict__ Ch2) {
  const int zi = blockIdx.z;
  const __half* Wmat = (zi == 0) ? Wm0 : (zi == 1) ? Wm1 : Wm2;
  const float* bias = (zi == 0) ? bz0 : (zi == 1) ? bz1 : bz2;

  __shared__ unsigned As[128 * GSW];
  __shared__ unsigned Bs[128 * GSW];
  const unsigned as_b = (unsigned)__cvta_generic_to_shared(As);
  const unsigned bs_b = (unsigned)__cvta_generic_to_shared(Bs);
  const int tid = threadIdx.x, lane = tid & 31, warp = tid >> 5;
  const int wm = warp >> 2, wn = warp & 3;
  const int m0 = blockIdx.y << 7, n0 = blockIdx.x << 7;
  const int K8 = D_MODEL / 8;  // 192 uint4 per fp16 row
  const uint4* A4 = (const uint4*)Ah;
  const uint4* W4 = (const uint4*)Wmat;
  const int la = lane & 7, lb = (lane >> 3) & 1, lc2 = lane >> 4;
  const int rq = lane >> 2, tq = lane & 3;

  // ldmatrix base addresses (bytes); per k16-step add 32*s
  unsigned a_base[4], b_base[2];
#pragma unroll
  for (int mf = 0; mf < 4; mf++)
    a_base[mf] =
        as_b + ((wm * 64 + mf * 16 + la + 8 * lb) * GSW + 4 * lc2) * 4;
#pragma unroll
  for (int np = 0; np < 2; np++)
    b_base[np] = bs_b + ((wn * 32 + np * 16 + la + 8 * lc2) * GSW + 4 * lb) * 4;

  float acc[4][4][4];
#pragma unroll
  for (int mf = 0; mf < 4; mf++)
#pragma unroll
    for (int nf = 0; nf < 4; nf++)
#pragma unroll
      for (int u = 0; u < 4; u++) acc[mf][nf][u] = 0.f;

  // loader mapping: row = ldrow + 32*i (0..127), granule = ldc8 (8 halves)
  const int ldrow = tid >> 3, ldc8 = tid & 7;

  // A-tile load for global row rg, granule column kc8 (8 halves at 8*kc8)
  auto load_a = [&](int rg, int kc8) -> uint4 {
    if (AMODE == 0) {
      return A4[(size_t)rg * K8 + kc8];
    } else if (AMODE == 1) {
      const float4* xf = (const float4*)Af;
      float4 t0 = xf[(size_t)rg * (D_MODEL / 4) + 2 * kc8];
      float4 t1 = xf[(size_t)rg * (D_MODEL / 4) + 2 * kc8 + 1];
      __half2 h0 = __floats2half2_rn(t0.x, t0.y);
      __half2 h1 = __floats2half2_rn(t0.z, t0.w);
      __half2 h2 = __floats2half2_rn(t1.x, t1.y);
      __half2 h3 = __floats2half2_rn(t1.z, t1.w);
      return make_uint4(*(unsigned*)&h0, *(unsigned*)&h1, *(unsigned*)&h2,
                        *(unsigned*)&h3);
    } else {
      int head = kc8 >> 4;  // 16 granules per head
      size_t ba = ((size_t)rg * N_HEADS + head) * 2;
      float ma = mlp[ba], la2 = mlp[ba + 1];
      float mb = mlp[ML_OFF + ba], lb2 = mlp[ML_OFF + ba + 1];
      float mm = fmaxf(ma, mb);
      float wa = ex2(ma - mm), wb = ex2(mb - mm);
      float inv = 1.f / (la2 * wa + lb2 * wb);
      wa *= inv;
      wb *= inv;
      const float4* pa = (const float4*)Oa + (size_t)rg * (D_MODEL / 4);
      const float4* pb = (const float4*)Ob + (size_t)rg * (D_MODEL / 4);
      float4 a0 = pa[2 * kc8], a1 = pa[2 * kc8 + 1];
      float4 b0 = pb[2 * kc8], b1 = pb[2 * kc8 + 1];
      __half2 h0 = __floats2half2_rn(a0.x * wa + b0.x * wb,
                                     a0.y * wa + b0.y * wb);
      __half2 h1 = __floats2half2_rn(a0.z * wa + b0.z * wb,
                                     a0.w * wa + b0.w * wb);
      __half2 h2 = __floats2half2_rn(a1.x * wa + b1.x * wb,
                                     a1.y * wa + b1.y * wb);
      __half2 h3 = __floats2half2_rn(a1.z * wa + b1.z * wb,
                                     a1.w * wa + b1.w * wb);
      return make_uint4(*(unsigned*)&h0, *(unsigned*)&h1, *(unsigned*)&h2,
                        *(unsigned*)&h3);
    }
  };

  uint4 ar[4], wr[4];
#pragma unroll
  for (int i = 0; i < 4; i++) {
    int r = ldrow + 32 * i;
    ar[i] = load_a(m0 + r, ldc8);
    wr[i] = W4[(size_t)(n0 + r) * K8 + ldc8];
  }

  for (int k0 = 0; k0 < D_MODEL; k0 += 64) {
    __syncthreads();
#pragma unroll
    for (int i = 0; i < 4; i++) {
      int r = ldrow + 32 * i;
      int base = r * GSW + 4 * ldc8;
      *(uint4*)&As[base] = ar[i];
      *(uint4*)&Bs[base] = wr[i];
    }
    __syncthreads();
    const int kn = (k0 + 64 < D_MODEL) ? (k0 + 64) : k0;
#pragma unroll
    for (int i = 0; i < 4; i++) {
      int r = ldrow + 32 * i;
      ar[i] = load_a(m0 + r, (kn >> 3) + ldc8);
      wr[i] = W4[(size_t)(n0 + r) * K8 + (kn >> 3) + ldc8];
    }
#pragma unroll
    for (int s = 0; s < 4; s++) {
      unsigned a[4][4], bq[2][4];
#pragma unroll
      for (int mf = 0; mf < 4; mf++)
        LDSM4(a[mf][0], a[mf][1], a[mf][2], a[mf][3], a_base[mf] + 32 * s);
#pragma unroll
      for (int np = 0; np < 2; np++)
        LDSM4(bq[np][0], bq[np][1], bq[np][2], bq[np][3], b_base[np] + 32 * s);
#pragma unroll
      for (int mf = 0; mf < 4; mf++)
#pragma unroll
        for (int np = 0; np < 2; np++) {
          mma16(acc[mf][2 * np], a[mf], &bq[np][0]);
          mma16(acc[mf][2 * np + 1], a[mf], &bq[np][2]);
        }
    }
  }

#pragma unroll
  for (int mf = 0; mf < 4; mf++) {
    int r = m0 + wm * 64 + mf * 16 + rq;
#pragma unroll
    for (int nf = 0; nf < 4; nf++) {
      int c = n0 + wn * 32 + 8 * nf + 2 * tq;
      float bb0 = bias[c], bb1 = bias[c + 1];
      float v00 = acc[mf][nf][0] + bb0, v01 = acc[mf][nf][1] + bb1;
      float v10 = acc[mf][nf][2] + bb0, v11 = acc[mf][nf][3] + bb1;
      if (zi == 2) {
        *(__half2*)&Ch2[(size_t)r * D_MODEL + c] = __floats2half2_rn(v00, v01);
        *(__half2*)&Ch2[(size_t)(r + 8) * D_MODEL + c] =
            __floats2half2_rn(v10, v11);
      } else {
        float* Cf = (zi == 0) ? Cf0 : Cf1;
        float2 o0 = {v00, v01};
        *(float2*)&Cf[(size_t)r * D_MODEL + c] = o0;
        float2 o1 = {v10, v11};
        *(float2*)&Cf[(size_t)(r + 8) * D_MODEL + c] = o1;
      }
    }
  }
}

// ---------------- fused RMSNorm (* g) + RoPE -> fp16 ----------------
// grid (L, 2): y=0 -> q (1/sqrt(d) * log2e folded), y=1 -> k
__global__ __launch_bounds__(256) void rmsnorm_rope(
    const float* __restrict__ bufq, const float* __restrict__ bufk,
    __half* __restrict__ outq, __half* __restrict__ outk,
    const float* __restrict__ gqp, const float* __restrict__ gkp,
    const int* __restrict__ grid_sizes,
    const float* __restrict__ fcos, const float* __restrict__ fsin) {
  const int t = blockIdx.x;
  const int tid = threadIdx.x;
  const int isq = (blockIdx.y == 0);
  const float* row = (isq ? bufq : bufk) + (size_t)t * D_MODEL;
  __half2* orow = (__half2*)((isq ? outq : outk) + (size_t)t * D_MODEL);
  const float* g = isq ? gqp : gkp;
  // q: 1/sqrt(128) * log2(e) so attention softmax runs in exp2 space
  const float post = isq ? (0.08838834764831845f * 1.4426950408889634f) : 1.0f;

  float ss = 0.f;
  for (int i = tid; i < D_MODEL; i += 256) {
    float xv = row[i];
    ss += xv * xv;
  }
#pragma unroll
  for (int o = 16; o; o >>= 1) ss += __shfl_xor_sync(0xffffffffu, ss, o);
  __shared__ float red[8];
  if ((tid & 31) == 0) red[tid >> 5] = ss;

  const int f = grid_sizes[0], h = grid_sizes[1], w = grid_sizes[2];
  const int sl = f * h * w;

  __shared__ float cs[C_HALF], sn[C_HALF];
  if (t < sl && tid < C_HALF) {
    int fi = t / (h * w);
    int rem = t - fi * h * w;
    int hi = rem / w;
    int wi = rem - hi * w;
    int jj = tid;
    int rowp = (jj < ROPE_C1) ? fi : ((jj < ROPE_C1 + ROPE_C2) ? hi : wi);
    cs[jj] = fcos[rowp * C_HALF + jj];
    sn[jj] = fsin[rowp * C_HALF + jj];
  }
  __syncthreads();
  float tot = red[0] + red[1] + red[2] + red[3] + red[4] + red[5] + red[6] + red[7];
  float rinv = rsqrtf(tot * (1.0f / D_MODEL) + 1e-6f);

  if (t < sl) {
    for (int p = tid; p < N_HEADS * C_HALF; p += 256) {
      int head = p >> 6;
      int jj = p & 63;
      int i0 = head * D_HEAD + 2 * jj;
      float y0 = row[i0] * rinv * g[i0];
      float y1 = row[i0 + 1] * rinv * g[i0 + 1];
      float cv = cs[jj], sv = sn[jj];
      orow[i0 >> 1] = __floats2half2_rn((y0 * cv - y1 * sv) * post,
                                        (y0 * sv + y1 * cv) * post);
    }
  } else {
    for (int p = tid; p < D_MODEL / 2; p += 256) {
      int i0 = 2 * p;
      orow[p] = __floats2half2_rn(row[i0] * rinv * g[i0] * post,
                                  row[i0 + 1] * rinv * g[i0 + 1] * post);
    }
  }
}

// ---------------- fp16 flash attention, split-KV (exp2 space) -------------
// grid (L/128, N_HEADS, 2): z selects KV half (32 tiles each).
// K/V double-buffered cp.async, P in registers.
// Writes UNNORMALIZED partial O (f32) + per-row (m, l) [log2 space].
#define QSW 68
#define KVW (64 * QSW)                    // words per K or V tile
#define ATTN_WORDS (128 * QSW + 4 * KVW)  // Q + 2x(K,V)
#define ATTN_SMEM (ATTN_WORDS * 4)

__global__ __launch_bounds__(256, 2) void attn_f16(
    const __half* __restrict__ qh, const __half* __restrict__ kh,
    const __half* __restrict__ vh, const int* __restrict__ seq_lens,
    float* __restrict__ opart0, float* __restrict__ opart1,
    float* __restrict__ ml) {
  extern __shared__ unsigned sm[];
  unsigned* Qs = sm;
  unsigned* Ks0 = Qs + 128 * QSW;  // buffers: Ks0, Vs0, Ks1, Vs1
  const unsigned qs_b = (unsigned)__cvta_generic_to_shared(Qs);
  const unsigned ks_b = (unsigned)__cvta_generic_to_shared(Ks0);
  const unsigned vs_b = ks_b + KVW * 4;
  const unsigned kvstr = 2 * KVW * 4;  // bytes between buffer pairs

  const int tid = threadIdx.x, lane = tid & 31, warp = tid >> 5;
  const int q0 = blockIdx.x << 7, head = blockIdx.y;
  const int kvz = blockIdx.z;
  const int kt0 = kvz << 5;  // first KV tile of this half
  const int seqlen = seq_lens[0];
  float* opart = kvz ? opart1 : opart0;
  const uint4* q4 = (const uint4*)qh;
  const uint4* k4 = (const uint4*)kh;
  const uint4* v4 = (const uint4*)vh;
  const int rs8 = D_MODEL / 8;
  const int h8 = head * 16;
  const int la = lane & 7, lb = (lane >> 3) & 1, lc2 = lane >> 4;
  const int rq = lane >> 2, tq = lane & 3;
  const int r_own = warp * 16 + rq;

  const unsigned a_off = qs_b + ((warp * 16 + la + 8 * lb) * QSW + 4 * lc2) * 4;
  const unsigned b_off0 = ks_b + ((la + 8 * lc2) * QSW + 4 * lb) * 4;
  const unsigned v_off0 = vs_b + ((la + 8 * lb) * QSW + 4 * lc2) * 4;

  // loader mapping: idx = tid + 256*i -> r = idx>>4, c8 = idx&15
  const int ldr = tid >> 4, ldc8 = tid & 15;

  // Q tile via cp.async (group 1)
#pragma unroll
  for (int i = 0; i < 8; i++) {
    int r = ldr + (i << 4);
    CP_ASYNC16(qs_b + (r * QSW + 4 * ldc8) * 4,
               (const void*)&q4[(size_t)(q0 + r) * rs8 + h8 + ldc8]);
  }
  CP_COMMIT();
  // K/V tile kt0 into buffer 0 (group 2)
#pragma unroll
  for (int i = 0; i < 4; i++) {
    int r = ldr + (i << 4);
    size_t grow = (size_t)((kt0 << 6) + r) * rs8 + h8 + ldc8;
    CP_ASYNC16(ks_b + (r * QSW + 4 * ldc8) * 4, (const void*)&k4[grow]);
    CP_ASYNC16(vs_b + (r * QSW + 4 * ldc8) * 4, (const void*)&v4[grow]);
  }
  CP_COMMIT();

  float m0r = -INFINITY, m1r = -INFINITY, l0 = 0.f, l1 = 0.f;
  float oac[16][4];
#pragma unroll
  for (int j = 0; j < 16; j++)
#pragma unroll
    for (int u = 0; u < 4; u++) oac[j][u] = 0.f;

  for (int it = 0; it < 32; it++) {
    const int kt = kt0 + it;
    const int b = it & 1;
    __syncthreads();  // all threads done reading buffer b^1 (iteration it-1)
    if (it < 31) {    // prefetch tile kt+1 into buffer b^1
#pragma unroll
      for (int i = 0; i < 4; i++) {
        int r = ldr + (i << 4);
        size_t grow = (size_t)(((kt + 1) << 6) + r) * rs8 + h8 + ldc8;
        unsigned boff = (b ^ 1) * kvstr + (r * QSW + 4 * ldc8) * 4;
        CP_ASYNC16(ks_b + boff, (const void*)&k4[grow]);
        CP_ASYNC16(vs_b + boff, (const void*)&v4[grow]);
      }
      CP_COMMIT();
      CP_WAIT1();  // tile kt (and Q) complete; kt+1 may be in flight
    } else {
      CP_WAIT0();
    }
    __syncthreads();  // tile kt visible to all threads

    const unsigned b_off = b_off0 + b * kvstr;
    const unsigned v_off = v_off0 + b * kvstr;

    // S = Q K^T : m16 (warp rows) x n64, k=128 in 8 k16-steps
    float sacc[8][4];
#pragma unroll
    for (int j = 0; j < 8; j++)
#pragma unroll
      for (int u = 0; u < 4; u++) sacc[j][u] = 0.f;

#pragma unroll
    for (int s = 0; s < 8; s++) {
      unsigned a[4];
      LDSM4(a[0], a[1], a[2], a[3], a_off + 32 * s);
#pragma unroll
      for (int jp = 0; jp < 4; jp++) {
        unsigned bb[4];
        LDSM4(bb[0], bb[1], bb[2], bb[3],
              b_off + jp * (16 * QSW * 4) + 32 * s);
        mma16(sacc[2 * jp], a, &bb[0]);
        mma16(sacc[2 * jp + 1], a, &bb[2]);
      }
    }

    // mask (ragged tail only)
    if (((kt << 6) + 63) >= seqlen) {
#pragma unroll
      for (int j = 0; j < 8; j++) {
        int c = (kt << 6) + (j << 3) + 2 * tq;
        if (c >= seqlen) { sacc[j][0] = -1e30f; sacc[j][2] = -1e30f; }
        if (c + 1 >= seqlen) { sacc[j][1] = -1e30f; sacc[j][3] = -1e30f; }
      }
    }

    // register softmax (exp2 space); P packed into PV A-fragments
    float mx0 = -INFINITY, mx1 = -INFINITY;
#pragma unroll
    for (int j = 0; j < 8; j++) {
      mx0 = fmaxf(mx0, fmaxf(sacc[j][0], sacc[j][1]));
      mx1 = fmaxf(mx1, fmaxf(sacc[j][2], sacc[j][3]));
    }
    mx0 = fmaxf(mx0, __shfl_xor_sync(0xffffffffu, mx0, 1));
    mx0 = fmaxf(mx0, __shfl_xor_sync(0xffffffffu, mx0, 2));
    mx1 = fmaxf(mx1, __shfl_xor_sync(0xffffffffu, mx1, 1));
    mx1 = fmaxf(mx1, __shfl_xor_sync(0xffffffffu, mx1, 2));
    float mn0 = fmaxf(m0r, mx0), mn1 = fmaxf(m1r, mx1);
    float co0 = ex2(m0r - mn0), co1 = ex2(m1r - mn1);
    float s0 = 0.f, s1 = 0.f;
    unsigned pfrag[4][4];
#pragma unroll
    for (int j = 0; j < 8; j++) {
      float p0 = ex2(sacc[j][0] - mn0);
      float p1 = ex2(sacc[j][1] - mn0);
      float p2 = ex2(sacc[j][2] - mn1);
      float p3 = ex2(sacc[j][3] - mn1);
      s0 += p0 + p1;
      s1 += p2 + p3;
      __half2 hp0 = __floats2half2_rn(p0, p1);  // row rq
      __half2 hp1 = __floats2half2_rn(p2, p3);  // row rq+8
      pfrag[j >> 1][(j & 1) * 2] = *(unsigned*)&hp0;
      pfrag[j >> 1][(j & 1) * 2 + 1] = *(unsigned*)&hp1;
    }
    s0 += __shfl_xor_sync(0xffffffffu, s0, 1);
    s0 += __shfl_xor_sync(0xffffffffu, s0, 2);
    s1 += __shfl_xor_sync(0xffffffffu, s1, 1);
    s1 += __shfl_xor_sync(0xffffffffu, s1, 2);
    l0 = l0 * co0 + s0;
    l1 = l1 * co1 + s1;
    m0r = mn0;
    m1r = mn1;
#pragma unroll
    for (int j = 0; j < 16; j++) {
      oac[j][0] *= co0;
      oac[j][1] *= co0;
      oac[j][2] *= co1;
      oac[j][3] *= co1;
    }

    // O += P V : m16 x n128, k=64 in 4 k16-steps; V via ldmatrix.trans
#pragma unroll
    for (int s = 0; s < 4; s++) {
#pragma unroll
      for (int jp = 0; jp < 8; jp++) {
        unsigned vb[4];
        LDSM4T(vb[0], vb[1], vb[2], vb[3],
               v_off + s * (16 * QSW * 4) + 32 * jp);
        mma16(oac[2 * jp], pfrag[s], &vb[0]);
        mma16(oac[2 * jp + 1], pfrag[s], &vb[2]);
      }
    }
  }

  // epilogue: store UNNORMALIZED partial O (f32) + (m, l) per row (log2)
  if (tq == 0) {
    size_t ba = (((size_t)q0 + r_own) * N_HEADS + head) * 2;
    ml[(size_t)kvz * ML_OFF + ba] = m0r;
    ml[(size_t)kvz * ML_OFF + ba + 1] = l0;
    size_t bb = (((size_t)q0 + r_own + 8) * N_HEADS + head) * 2;
    ml[(size_t)kvz * ML_OFF + bb] = m1r;
    ml[(size_t)kvz * ML_OFF + bb + 1] = l1;
  }
#pragma unroll
  for (int j = 0; j < 16; j++) {
    int c = head * D_HEAD + 8 * j + 2 * tq;
    float2 a = {oac[j][0], oac[j][1]};
    *(float2*)&opart[(size_t)(q0 + r_own) * D_MODEL + c] = a;
    float2 b = {oac[j][2], oac[j][3]};
    *(float2*)&opart[(size_t)(q0 + r_own + 8) * D_MODEL + c] = b;
  }
}

// ---------------- launch ----------------
extern "C" void kernel_launch(void* const* d_in, const int* in_sizes, int n_in,
                              void* d_out, int out_size) {
  const float* x = (const float*)d_in[0];
  const int* seq_lens = (const int*)d_in[1];
  const int* grid_sizes = (const int*)d_in[2];
  const float* fcos = (const float*)d_in[3];
  const float* fsin = (const float*)d_in[4];
  const float* Wq = (const float*)d_in[5];
  const float* bq = (const float*)d_in[6];
  const float* Wk = (const float*)d_in[7];
  const float* bk = (const float*)d_in[8];
  const float* Wv = (const float*)d_in[9];
  const float* bv = (const float*)d_in[10];
  const float* Wo = (const float*)d_in[11];
  const float* bo = (const float*)d_in[12];
  const float* gq = (const float*)d_in[13];
  const float* gk = (const float*)d_in[14];
  float* out = (float*)d_out;

  void *pq, *pk, *pqh, *pkh, *pvh, *pwh, *pml;
  cudaGetSymbolAddress(&pq, g_q);
  cudaGetSymbolAddress(&pk, g_k);
  cudaGetSymbolAddress(&pqh, g_qh);
  cudaGetSymbolAddress(&pkh, g_kh);
  cudaGetSymbolAddress(&pvh, g_vh);
  cudaGetSymbolAddress(&pwh, g_wh);
  cudaGetSymbolAddress(&pml, g_ml);
  float* fq = (float*)pq;
  float* fk = (float*)pk;
  __half* fqh = (__half*)pqh;
  __half* fkh = (__half*)pkh;
  __half* fvh = (__half*)pvh;
  __half* fwh = (__half*)pwh;
  float* fml = (float*)pml;

  // convert weights to fp16 (x converts inline in the QKV GEMM loader)
  {
    dim3 gr((W_ELEMS / 4 + 255) / 256, 1, 4);
    to_half<<<gr, 256>>>(Wq, Wk, Wv, Wo);
  }

  // fused QKV projection (A = f32 x, converted on load):
  // z0->q f32, z1->k f32, z2->v fp16
  dim3 gqkv(D_MODEL / 128, L_SEQ / 128, 3);
  gemm_f16<1><<<gqkv, 256>>>(nullptr, x, nullptr, nullptr, nullptr,
                             fwh, fwh + W_ELEMS, fwh + 2 * W_ELEMS,
                             bq, bk, bv, fq, fk, fvh);

  rmsnorm_rope<<<dim3(L_SEQ, 2), 256>>>(fq, fk, fqh, fkh, gq, gk, grid_sizes,
                                        fcos, fsin);

  // split-KV attention: partial O into g_q (z=0) / g_k (z=1) [now free]
  cudaFuncSetAttribute(attn_f16, cudaFuncAttributeMaxDynamicSharedMemorySize,
                       ATTN_SMEM);
  attn_f16<<<dim3(L_SEQ / 128, N_HEADS, 2), 256, ATTN_SMEM>>>(
      fqh, fkh, fvh, seq_lens, fq, fk, fml);

  // output projection with FUSED split-KV merge in the A-loader (zi=0 -> f32)
  dim3 go(D_MODEL / 128, L_SEQ / 128, 1);
  gemm_f16<2><<<go, 256>>>(nullptr, nullptr, fq, fk, fml,
                           fwh + 3 * W_ELEMS, fwh + 3 * W_ELEMS,
                           fwh + 3 * W_ELEMS, bo, bo, bo, out, out, fvh);
}

// round 17
// speedup vs baseline: 1.1834x; 1.1834x over previous
#include <cuda_runtime.h>
#include <cuda_fp16.h>
#include <cstdint>
#include <stdint.h>
#include <math.h>

#define L_SEQ 4096
#define D_MODEL 1536
#define N_HEADS 12
#define D_HEAD 128
#define C_HALF 64   // d/2
#define ROPE_C1 22
#define ROPE_C2 21
#define W_ELEMS (D_MODEL * D_MODEL)
#define ML_OFF ((size_t)L_SEQ * N_HEADS * 2)

// ---------------- scratch (no allocations allowed) ----------------
__device__ float g_q[L_SEQ * D_MODEL];   // f32 q from GEMM; later: partial O (z=0)
__device__ float g_k[L_SEQ * D_MODEL];   // f32 k from GEMM; later: partial O (z=1)
__device__ __half g_qh[L_SEQ * D_MODEL]; // fp16 q (normed+rope+scaled)
__device__ __half g_kh[L_SEQ * D_MODEL]; // fp16 k
__device__ __half g_vh[L_SEQ * D_MODEL]; // fp16 v
__device__ __half g_ao[L_SEQ * D_MODEL]; // fp16 attention output
__device__ __half g_xh[L_SEQ * D_MODEL]; // fp16 x
__device__ __half g_wh[4 * W_ELEMS];     // fp16 Wq,Wk,Wv,Wo
__device__ float g_ml[2 * L_SEQ * N_HEADS * 2];  // (m,l) per z,row,head (log2)

// ---------------- helpers ----------------
__device__ __forceinline__ float ex2(float x) {
  float y;
  asm("ex2.approx.f32 %0, %1;" : "=f"(y) : "f"(x));
  return y;
}

__device__ __forceinline__ void mma16(float* c, const unsigned* a,
                                      const unsigned* b) {
  asm volatile(
      "mma.sync.aligned.m16n8k16.row.col.f32.f16.f16.f32 "
      "{%0,%1,%2,%3},{%4,%5,%6,%7},{%8,%9},{%0,%1,%2,%3};\n"
      : "+f"(c[0]), "+f"(c[1]), "+f"(c[2]), "+f"(c[3])
      : "r"(a[0]), "r"(a[1]), "r"(a[2]), "r"(a[3]), "r"(b[0]), "r"(b[1]));
}

#define LDSM4(r0, r1, r2, r3, addr)                                      \
  asm volatile("ldmatrix.sync.aligned.m8n8.x4.shared.b16 {%0,%1,%2,%3},[%4];" \
               : "=r"(r0), "=r"(r1), "=r"(r2), "=r"(r3) : "r"(addr))
#define LDSM4T(r0, r1, r2, r3, addr)                                     \
  asm volatile(                                                          \
      "ldmatrix.sync.aligned.m8n8.x4.trans.shared.b16 {%0,%1,%2,%3},[%4];" \
      : "=r"(r0), "=r"(r1), "=r"(r2), "=r"(r3) : "r"(addr))

// cp.async helpers (16B, cache-global)
#define CP_ASYNC16(dst, src)                                        \
  asm volatile("cp.async.cg.shared.global [%0], [%1], 16;" ::       \
                   "r"(dst), "l"(src))
#define CP_COMMIT() asm volatile("cp.async.commit_group;" ::: "memory")
#define CP_WAIT0() asm volatile("cp.async.wait_group 0;" ::: "memory")
#define CP_WAIT1() asm volatile("cp.async.wait_group 1;" ::: "memory")

// ---------------- fp16 conversion of weights + x ----------------
__global__ __launch_bounds__(256) void to_half(
    const float* __restrict__ wq, const float* __restrict__ wk,
    const float* __restrict__ wv, const float* __restrict__ wo,
    const float* __restrict__ x) {
  const int zi = blockIdx.z;
  const float4* src;
  __half2* dst;
  int n4;
  if (zi < 4) {
    src = (const float4*)((zi == 0) ? wq : (zi == 1) ? wk : (zi == 2) ? wv
                                                                      : wo);
    dst = ((__half2*)g_wh) + (size_t)zi * (W_ELEMS / 2);
    n4 = W_ELEMS / 4;
  } else {
    src = (const float4*)x;
    dst = (__half2*)g_xh;
    n4 = (L_SEQ * D_MODEL) / 4;
  }
  int idx = blockIdx.x * 256 + threadIdx.x;
  if (idx < n4) {
    float4 t = src[idx];
    dst[2 * idx] = __floats2half2_rn(t.x, t.y);
    dst[2 * idx + 1] = __floats2half2_rn(t.z, t.w);
  }
}

// ---------------- fp16 GEMM: C[M,N] = A * W^T + bias ----------------
// 128x128 tile, BK=64, 256 threads (8 warps, 2m x 4n), warp 64x32.
// zi selects weights/bias/output; zi==2 writes fp16 (v), else fp32.
#define GSW 36  // row stride in words (64 halves + 8 pad = 144B)
__global__ __launch_bounds__(256, 2) void gemm_f16(
    const __half* __restrict__ Ah,
    const __half* __restrict__ Wm0, const __half* __restrict__ Wm1,
    const __half* __restrict__ Wm2,
    const float* __restrict__ bz0, const float* __restrict__ bz1,
    const float* __restrict__ bz2,
    float* __restrict__ Cf0, float* __restrict__ Cf1,
    __half* __restrict__ Ch2) {
  const int zi = blockIdx.z;
  const __half* Wmat = (zi == 0) ? Wm0 : (zi == 1) ? Wm1 : Wm2;
  const float* bias = (zi == 0) ? bz0 : (zi == 1) ? bz1 : bz2;

  __shared__ unsigned As[128 * GSW];
  __shared__ unsigned Bs[128 * GSW];
  const unsigned as_b = (unsigned)__cvta_generic_to_shared(As);
  const unsigned bs_b = (unsigned)__cvta_generic_to_shared(Bs);
  const int tid = threadIdx.x, lane = tid & 31, warp = tid >> 5;
  const int wm = warp >> 2, wn = warp & 3;
  const int m0 = blockIdx.y << 7, n0 = blockIdx.x << 7;
  const int K8 = D_MODEL / 8;  // 192 uint4 per row
  const uint4* A4 = (const uint4*)Ah;
  const uint4* W4 = (const uint4*)Wmat;
  const int la = lane & 7, lb = (lane >> 3) & 1, lc2 = lane >> 4;
  const int rq = lane >> 2, tq = lane & 3;

  // ldmatrix base addresses (bytes); per k16-step add 32*s
  unsigned a_base[4], b_base[2];
#pragma unroll
  for (int mf = 0; mf < 4; mf++)
    a_base[mf] =
        as_b + ((wm * 64 + mf * 16 + la + 8 * lb) * GSW + 4 * lc2) * 4;
#pragma unroll
  for (int np = 0; np < 2; np++)
    b_base[np] = bs_b + ((wn * 32 + np * 16 + la + 8 * lc2) * GSW + 4 * lb) * 4;

  float acc[4][4][4];
#pragma unroll
  for (int mf = 0; mf < 4; mf++)
#pragma unroll
    for (int nf = 0; nf < 4; nf++)
#pragma unroll
      for (int u = 0; u < 4; u++) acc[mf][nf][u] = 0.f;

  // loader mapping: idx = tid + 256*i -> row = idx>>3 (0..127), c8 = idx&7
  const int ldrow = tid >> 3, ldc8 = tid & 7;
  uint4 ar[4], wr[4];
#pragma unroll
  for (int i = 0; i < 4; i++) {
    int r = ldrow + 32 * i;
    ar[i] = A4[(size_t)(m0 + r) * K8 + ldc8];
    wr[i] = W4[(size_t)(n0 + r) * K8 + ldc8];
  }

  for (int k0 = 0; k0 < D_MODEL; k0 += 64) {
    __syncthreads();
#pragma unroll
    for (int i = 0; i < 4; i++) {
      int r = ldrow + 32 * i;
      int base = r * GSW + 4 * ldc8;
      *(uint4*)&As[base] = ar[i];
      *(uint4*)&Bs[base] = wr[i];
    }
    __syncthreads();
    const int kn = (k0 + 64 < D_MODEL) ? (k0 + 64) : k0;
#pragma unroll
    for (int i = 0; i < 4; i++) {
      int r = ldrow + 32 * i;
      ar[i] = A4[(size_t)(m0 + r) * K8 + (kn >> 3) + ldc8];
      wr[i] = W4[(size_t)(n0 + r) * K8 + (kn >> 3) + ldc8];
    }
#pragma unroll
    for (int s = 0; s < 4; s++) {
      unsigned a[4][4], bq[2][4];
#pragma unroll
      for (int mf = 0; mf < 4; mf++)
        LDSM4(a[mf][0], a[mf][1], a[mf][2], a[mf][3], a_base[mf] + 32 * s);
#pragma unroll
      for (int np = 0; np < 2; np++)
        LDSM4(bq[np][0], bq[np][1], bq[np][2], bq[np][3], b_base[np] + 32 * s);
#pragma unroll
      for (int mf = 0; mf < 4; mf++)
#pragma unroll
        for (int np = 0; np < 2; np++) {
          mma16(acc[mf][2 * np], a[mf], &bq[np][0]);
          mma16(acc[mf][2 * np + 1], a[mf], &bq[np][2]);
        }
    }
  }

#pragma unroll
  for (int mf = 0; mf < 4; mf++) {
    int r = m0 + wm * 64 + mf * 16 + rq;
#pragma unroll
    for (int nf = 0; nf < 4; nf++) {
      int c = n0 + wn * 32 + 8 * nf + 2 * tq;
      float bb0 = bias[c], bb1 = bias[c + 1];
      float v00 = acc[mf][nf][0] + bb0, v01 = acc[mf][nf][1] + bb1;
      float v10 = acc[mf][nf][2] + bb0, v11 = acc[mf][nf][3] + bb1;
      if (zi == 2) {
        *(__half2*)&Ch2[(size_t)r * D_MODEL + c] = __floats2half2_rn(v00, v01);
        *(__half2*)&Ch2[(size_t)(r + 8) * D_MODEL + c] =
            __floats2half2_rn(v10, v11);
      } else {
        float* Cf = (zi == 0) ? Cf0 : Cf1;
        float2 o0 = {v00, v01};
        *(float2*)&Cf[(size_t)r * D_MODEL + c] = o0;
        float2 o1 = {v10, v11};
        *(float2*)&Cf[(size_t)(r + 8) * D_MODEL + c] = o1;
      }
    }
  }
}

// ---------------- fused RMSNorm (* g) + RoPE -> fp16 ----------------
// grid (L, 2): y=0 -> q (1/sqrt(d) * log2e folded), y=1 -> k
__global__ __launch_bounds__(256) void rmsnorm_rope(
    const float* __restrict__ bufq, const float* __restrict__ bufk,
    __half* __restrict__ outq, __half* __restrict__ outk,
    const float* __restrict__ gqp, const float* __restrict__ gkp,
    const int* __restrict__ grid_sizes,
    const float* __restrict__ fcos, const float* __restrict__ fsin) {
  const int t = blockIdx.x;
  const int tid = threadIdx.x;
  const int isq = (blockIdx.y == 0);
  const float* row = (isq ? bufq : bufk) + (size_t)t * D_MODEL;
  __half2* orow = (__half2*)((isq ? outq : outk) + (size_t)t * D_MODEL);
  const float* g = isq ? gqp : gkp;
  // q: 1/sqrt(128) * log2(e) so attention softmax runs in exp2 space
  const float post = isq ? (0.08838834764831845f * 1.4426950408889634f) : 1.0f;

  float ss = 0.f;
  for (int i = tid; i < D_MODEL; i += 256) {
    float xv = row[i];
    ss += xv * xv;
  }
#pragma unroll
  for (int o = 16; o; o >>= 1) ss += __shfl_xor_sync(0xffffffffu, ss, o);
  __shared__ float red[8];
  if ((tid & 31) == 0) red[tid >> 5] = ss;

  const int f = grid_sizes[0], h = grid_sizes[1], w = grid_sizes[2];
  const int sl = f * h * w;

  __shared__ float cs[C_HALF], sn[C_HALF];
  if (t < sl && tid < C_HALF) {
    int fi = t / (h * w);
    int rem = t - fi * h * w;
    int hi = rem / w;
    int wi = rem - hi * w;
    int jj = tid;
    int rowp = (jj < ROPE_C1) ? fi : ((jj < ROPE_C1 + ROPE_C2) ? hi : wi);
    cs[jj] = fcos[rowp * C_HALF + jj];
    sn[jj] = fsin[rowp * C_HALF + jj];
  }
  __syncthreads();
  float tot = red[0] + red[1] + red[2] + red[3] + red[4] + red[5] + red[6] + red[7];
  float rinv = rsqrtf(tot * (1.0f / D_MODEL) + 1e-6f);

  if (t < sl) {
    for (int p = tid; p < N_HEADS * C_HALF; p += 256) {
      int head = p >> 6;
      int jj = p & 63;
      int i0 = head * D_HEAD + 2 * jj;
      float y0 = row[i0] * rinv * g[i0];
      float y1 = row[i0 + 1] * rinv * g[i0 + 1];
      float cv = cs[jj], sv = sn[jj];
      orow[i0 >> 1] = __floats2half2_rn((y0 * cv - y1 * sv) * post,
                                        (y0 * sv + y1 * cv) * post);
    }
  } else {
    for (int p = tid; p < D_MODEL / 2; p += 256) {
      int i0 = 2 * p;
      orow[p] = __floats2half2_rn(row[i0] * rinv * g[i0] * post,
                                  row[i0 + 1] * rinv * g[i0 + 1] * post);
    }
  }
}

// ---------------- fp16 flash attention, split-KV (exp2 space) -------------
// grid (L/128, N_HEADS, 2): z selects KV half (32 tiles each).
// K/V double-buffered cp.async, P in registers.
// Writes UNNORMALIZED partial O (f32) + per-row (m, l) [log2 space].
#define QSW 68
#define KVW (64 * QSW)                    // words per K or V tile
#define ATTN_WORDS (128 * QSW + 4 * KVW)  // Q + 2x(K,V)
#define ATTN_SMEM (ATTN_WORDS * 4)

__global__ __launch_bounds__(256, 2) void attn_f16(
    const __half* __restrict__ qh, const __half* __restrict__ kh,
    const __half* __restrict__ vh, const int* __restrict__ seq_lens,
    float* __restrict__ opart0, float* __restrict__ opart1,
    float* __restrict__ ml) {
  extern __shared__ unsigned sm[];
  unsigned* Qs = sm;
  unsigned* Ks0 = Qs + 128 * QSW;  // buffers: Ks0, Vs0, Ks1, Vs1
  const unsigned qs_b = (unsigned)__cvta_generic_to_shared(Qs);
  const unsigned ks_b = (unsigned)__cvta_generic_to_shared(Ks0);
  const unsigned vs_b = ks_b + KVW * 4;
  const unsigned kvstr = 2 * KVW * 4;  // bytes between buffer pairs

  const int tid = threadIdx.x, lane = tid & 31, warp = tid >> 5;
  const int q0 = blockIdx.x << 7, head = blockIdx.y;
  const int kvz = blockIdx.z;
  const int kt0 = kvz << 5;  // first KV tile of this half
  const int seqlen = seq_lens[0];
  float* opart = kvz ? opart1 : opart0;
  const uint4* q4 = (const uint4*)qh;
  const uint4* k4 = (const uint4*)kh;
  const uint4* v4 = (const uint4*)vh;
  const int rs8 = D_MODEL / 8;
  const int h8 = head * 16;
  const int la = lane & 7, lb = (lane >> 3) & 1, lc2 = lane >> 4;
  const int rq = lane >> 2, tq = lane & 3;
  const int r_own = warp * 16 + rq;

  const unsigned a_off = qs_b + ((warp * 16 + la + 8 * lb) * QSW + 4 * lc2) * 4;
  const unsigned b_off0 = ks_b + ((la + 8 * lc2) * QSW + 4 * lb) * 4;
  const unsigned v_off0 = vs_b + ((la + 8 * lb) * QSW + 4 * lc2) * 4;

  // loader mapping: idx = tid + 256*i -> r = idx>>4, c8 = idx&15
  const int ldr = tid >> 4, ldc8 = tid & 15;

  // Q tile via cp.async (group 1)
#pragma unroll
  for (int i = 0; i < 8; i++) {
    int r = ldr + (i << 4);
    CP_ASYNC16(qs_b + (r * QSW + 4 * ldc8) * 4,
               (const void*)&q4[(size_t)(q0 + r) * rs8 + h8 + ldc8]);
  }
  CP_COMMIT();
  // K/V tile kt0 into buffer 0 (group 2)
#pragma unroll
  for (int i = 0; i < 4; i++) {
    int r = ldr + (i << 4);
    size_t grow = (size_t)((kt0 << 6) + r) * rs8 + h8 + ldc8;
    CP_ASYNC16(ks_b + (r * QSW + 4 * ldc8) * 4, (const void*)&k4[grow]);
    CP_ASYNC16(vs_b + (r * QSW + 4 * ldc8) * 4, (const void*)&v4[grow]);
  }
  CP_COMMIT();

  float m0r = -INFINITY, m1r = -INFINITY, l0 = 0.f, l1 = 0.f;
  float oac[16][4];
#pragma unroll
  for (int j = 0; j < 16; j++)
#pragma unroll
    for (int u = 0; u < 4; u++) oac[j][u] = 0.f;

  for (int it = 0; it < 32; it++) {
    const int kt = kt0 + it;
    const int b = it & 1;
    __syncthreads();  // all threads done reading buffer b^1 (iteration it-1)
    if (it < 31) {    // prefetch tile kt+1 into buffer b^1
#pragma unroll
      for (int i = 0; i < 4; i++) {
        int r = ldr + (i << 4);
        size_t grow = (size_t)(((kt + 1) << 6) + r) * rs8 + h8 + ldc8;
        unsigned boff = (b ^ 1) * kvstr + (r * QSW + 4 * ldc8) * 4;
        CP_ASYNC16(ks_b + boff, (const void*)&k4[grow]);
        CP_ASYNC16(vs_b + boff, (const void*)&v4[grow]);
      }
      CP_COMMIT();
      CP_WAIT1();  // tile kt (and Q) complete; kt+1 may be in flight
    } else {
      CP_WAIT0();
    }
    __syncthreads();  // tile kt visible to all threads

    const unsigned b_off = b_off0 + b * kvstr;
    const unsigned v_off = v_off0 + b * kvstr;

    // S = Q K^T : m16 (warp rows) x n64, k=128 in 8 k16-steps
    float sacc[8][4];
#pragma unroll
    for (int j = 0; j < 8; j++)
#pragma unroll
      for (int u = 0; u < 4; u++) sacc[j][u] = 0.f;

#pragma unroll
    for (int s = 0; s < 8; s++) {
      unsigned a[4];
      LDSM4(a[0], a[1], a[2], a[3], a_off + 32 * s);
#pragma unroll
      for (int jp = 0; jp < 4; jp++) {
        unsigned bb[4];
        LDSM4(bb[0], bb[1], bb[2], bb[3],
              b_off + jp * (16 * QSW * 4) + 32 * s);
        mma16(sacc[2 * jp], a, &bb[0]);
        mma16(sacc[2 * jp + 1], a, &bb[2]);
      }
    }

    // mask (ragged tail only)
    if (((kt << 6) + 63) >= seqlen) {
#pragma unroll
      for (int j = 0; j < 8; j++) {
        int c = (kt << 6) + (j << 3) + 2 * tq;
        if (c >= seqlen) { sacc[j][0] = -1e30f; sacc[j][2] = -1e30f; }
        if (c + 1 >= seqlen) { sacc[j][1] = -1e30f; sacc[j][3] = -1e30f; }
      }
    }

    // register softmax (exp2 space); P packed into PV A-fragments
    float mx0 = -INFINITY, mx1 = -INFINITY;
#pragma unroll
    for (int j = 0; j < 8; j++) {
      mx0 = fmaxf(mx0, fmaxf(sacc[j][0], sacc[j][1]));
      mx1 = fmaxf(mx1, fmaxf(sacc[j][2], sacc[j][3]));
    }
    mx0 = fmaxf(mx0, __shfl_xor_sync(0xffffffffu, mx0, 1));
    mx0 = fmaxf(mx0, __shfl_xor_sync(0xffffffffu, mx0, 2));
    mx1 = fmaxf(mx1, __shfl_xor_sync(0xffffffffu, mx1, 1));
    mx1 = fmaxf(mx1, __shfl_xor_sync(0xffffffffu, mx1, 2));
    float mn0 = fmaxf(m0r, mx0), mn1 = fmaxf(m1r, mx1);
    float co0 = ex2(m0r - mn0), co1 = ex2(m1r - mn1);
    float s0 = 0.f, s1 = 0.f;
    unsigned pfrag[4][4];
#pragma unroll
    for (int j = 0; j < 8; j++) {
      float p0 = ex2(sacc[j][0] - mn0);
      float p1 = ex2(sacc[j][1] - mn0);
      float p2 = ex2(sacc[j][2] - mn1);
      float p3 = ex2(sacc[j][3] - mn1);
      s0 += p0 + p1;
      s1 += p2 + p3;
      __half2 hp0 = __floats2half2_rn(p0, p1);  // row rq
      __half2 hp1 = __floats2half2_rn(p2, p3);  // row rq+8
      pfrag[j >> 1][(j & 1) * 2] = *(unsigned*)&hp0;
      pfrag[j >> 1][(j & 1) * 2 + 1] = *(unsigned*)&hp1;
    }
    s0 += __shfl_xor_sync(0xffffffffu, s0, 1);
    s0 += __shfl_xor_sync(0xffffffffu, s0, 2);
    s1 += __shfl_xor_sync(0xffffffffu, s1, 1);
    s1 += __shfl_xor_sync(0xffffffffu, s1, 2);
    l0 = l0 * co0 + s0;
    l1 = l1 * co1 + s1;
    m0r = mn0;
    m1r = mn1;
#pragma unroll
    for (int j = 0; j < 16; j++) {
      oac[j][0] *= co0;
      oac[j][1] *= co0;
      oac[j][2] *= co1;
      oac[j][3] *= co1;
    }

    // O += P V : m16 x n128, k=64 in 4 k16-steps; V via ldmatrix.trans
#pragma unroll
    for (int s = 0; s < 4; s++) {
#pragma unroll
      for (int jp = 0; jp < 8; jp++) {
        unsigned vb[4];
        LDSM4T(vb[0], vb[1], vb[2], vb[3],
               v_off + s * (16 * QSW * 4) + 32 * jp);
        mma16(oac[2 * jp], pfrag[s], &vb[0]);
        mma16(oac[2 * jp + 1], pfrag[s], &vb[2]);
      }
    }
  }

  // epilogue: store UNNORMALIZED partial O (f32) + (m, l) per row (log2)
  if (tq == 0) {
    size_t ba = (((size_t)q0 + r_own) * N_HEADS + head) * 2;
    ml[(size_t)kvz * ML_OFF + ba] = m0r;
    ml[(size_t)kvz * ML_OFF + ba + 1] = l0;
    size_t bb = (((size_t)q0 + r_own + 8) * N_HEADS + head) * 2;
    ml[(size_t)kvz * ML_OFF + bb] = m1r;
    ml[(size_t)kvz * ML_OFF + bb + 1] = l1;
  }
#pragma unroll
  for (int j = 0; j < 16; j++) {
    int c = head * D_HEAD + 8 * j + 2 * tq;
    float2 a = {oac[j][0], oac[j][1]};
    *(float2*)&opart[(size_t)(q0 + r_own) * D_MODEL + c] = a;
    float2 b = {oac[j][2], oac[j][3]};
    *(float2*)&opart[(size_t)(q0 + r_own + 8) * D_MODEL + c] = b;
  }
}

// ---------------- merge two split-KV partials -> fp16 (log2 space) --------
__global__ __launch_bounds__(256) void attn_merge(
    const float* __restrict__ oa, const float* __restrict__ ob,
    const float* __restrict__ ml, __half* __restrict__ out) {
  int idx = blockIdx.x * 256 + threadIdx.x;  // float4 unit
  if (idx >= (L_SEQ * D_MODEL) / 4) return;
  int col4 = idx % (D_MODEL / 4);
  int row = idx / (D_MODEL / 4);
  int head = col4 >> 5;  // 32 float4 per head (128 dims)
  size_t ba = ((size_t)row * N_HEADS + head) * 2;
  float ma = ml[ba], la = ml[ba + 1];
  float mb = ml[ML_OFF + ba];
  float lb = ml[ML_OFF + ba + 1];
  float m = fmaxf(ma, mb);
  float wa = ex2(ma - m), wb = ex2(mb - m);
  float inv = 1.f / (la * wa + lb * wb);
  wa *= inv;
  wb *= inv;
  float4 a = ((const float4*)oa)[idx];
  float4 b = ((const float4*)ob)[idx];
  __half2 h0 = __floats2half2_rn(a.x * wa + b.x * wb, a.y * wa + b.y * wb);
  __half2 h1 = __floats2half2_rn(a.z * wa + b.z * wb, a.w * wa + b.w * wb);
  ((__half2*)out)[2 * idx] = h0;
  ((__half2*)out)[2 * idx + 1] = h1;
}

// ---------------- launch ----------------
extern "C" void kernel_launch(void* const* d_in, const int* in_sizes, int n_in,
                              void* d_out, int out_size) {
  const float* x = (const float*)d_in[0];
  const int* seq_lens = (const int*)d_in[1];
  const int* grid_sizes = (const int*)d_in[2];
  const float* fcos = (const float*)d_in[3];
  const float* fsin = (const float*)d_in[4];
  const float* Wq = (const float*)d_in[5];
  const float* bq = (const float*)d_in[6];
  const float* Wk = (const float*)d_in[7];
  const float* bk = (const float*)d_in[8];
  const float* Wv = (const float*)d_in[9];
  const float* bv = (const float*)d_in[10];
  const float* Wo = (const float*)d_in[11];
  const float* bo = (const float*)d_in[12];
  const float* gq = (const float*)d_in[13];
  const float* gk = (const float*)d_in[14];
  float* out = (float*)d_out;

  void *pq, *pk, *pqh, *pkh, *pvh, *pao, *pxh, *pwh, *pml;
  cudaGetSymbolAddress(&pq, g_q);
  cudaGetSymbolAddress(&pk, g_k);
  cudaGetSymbolAddress(&pqh, g_qh);
  cudaGetSymbolAddress(&pkh, g_kh);
  cudaGetSymbolAddress(&pvh, g_vh);
  cudaGetSymbolAddress(&pao, g_ao);
  cudaGetSymbolAddress(&pxh, g_xh);
  cudaGetSymbolAddress(&pwh, g_wh);
  cudaGetSymbolAddress(&pml, g_ml);
  float* fq = (float*)pq;
  float* fk = (float*)pk;
  __half* fqh = (__half*)pqh;
  __half* fkh = (__half*)pkh;
  __half* fvh = (__half*)pvh;
  __half* fao = (__half*)pao;
  __half* fxh = (__half*)pxh;
  __half* fwh = (__half*)pwh;
  float* fml = (float*)pml;

  // convert weights + x to fp16
  {
    int n4max = (L_SEQ * D_MODEL) / 4;
    dim3 gr((n4max + 255) / 256, 1, 5);
    to_half<<<gr, 256>>>(Wq, Wk, Wv, Wo, x);
  }

  // fused QKV projection: z0->q f32, z1->k f32, z2->v fp16
  dim3 gqkv(D_MODEL / 128, L_SEQ / 128, 3);
  gemm_f16<<<gqkv, 256>>>(fxh, fwh, fwh + W_ELEMS, fwh + 2 * W_ELEMS,
                          bq, bk, bv, fq, fk, fvh);

  rmsnorm_rope<<<dim3(L_SEQ, 2), 256>>>(fq, fk, fqh, fkh, gq, gk, grid_sizes,
                                        fcos, fsin);

  // split-KV attention: partial O into g_q (z=0) / g_k (z=1) [now free]
  cudaFuncSetAttribute(attn_f16, cudaFuncAttributeMaxDynamicSharedMemorySize,
                       ATTN_SMEM);
  attn_f16<<<dim3(L_SEQ / 128, N_HEADS, 2), 256, ATTN_SMEM>>>(
      fqh, fkh, fvh, seq_lens, fq, fk, fml);

  // merge partials -> fp16 attention output
  attn_merge<<<(L_SEQ * D_MODEL / 4 + 255) / 256, 256>>>(fq, fk, fml, fao);

  // output projection (zi=0 -> f32 out)
  dim3 go(D_MODEL / 128, L_SEQ / 128, 1);
  gemm_f16<<<go, 256>>>(fao, fwh + 3 * W_ELEMS, fwh + 3 * W_ELEMS,
                        fwh + 3 * W_ELEMS, bo, bo, bo, out, out, fvh);
}